// round 1
// baseline (speedup 1.0000x reference)
#include <cuda_runtime.h>

#define NN   50000
#define EE   800000
#define FIN  64
#define HID  128
#define NCLS 10
#define NG   128
#define KTOP 400000
#define MAX_TIES 4096

struct SelState {
    unsigned prefix;
    int kk;
    unsigned threshold;
    int needed;
    int tie_count;
};

struct __align__(16) Scratch {
    float h [(size_t)NN * HID];
    float Ai[(size_t)NN * HID];
    float At[(size_t)NN * HID];
    float Ar[(size_t)NN * HID];
    float T [(size_t)NN * HID];
    float X [(size_t)NN * HID];
    float ew[EE];
    unsigned char flag[EE];
    unsigned hist[2048];
    int tie[MAX_TIES];
    float pool[NG * HID];
    SelState st;
};
__device__ Scratch g_s;

// ---------------------------------------------------------------------------
// vector fp32 reduction to global (sm_90+)
// ---------------------------------------------------------------------------
__device__ __forceinline__ void red4(float* addr, float4 v) {
    asm volatile("red.global.add.v4.f32 [%0], {%1,%2,%3,%4};"
                 :: "l"(addr), "f"(v.x), "f"(v.y), "f"(v.z), "f"(v.w)
                 : "memory");
}

__device__ __forceinline__ unsigned fkey(float f) {
    unsigned u = __float_as_uint(f);
    return (u & 0x80000000u) ? ~u : (u | 0x80000000u);
}

// ---------------------------------------------------------------------------
// zero / init
// ---------------------------------------------------------------------------
__global__ void zero_init(Scratch* s) {
    size_t idx = (size_t)blockIdx.x * blockDim.x + threadIdx.x;
    size_t stride = (size_t)gridDim.x * blockDim.x;
    const size_t nf4 = (size_t)NN * HID / 4;
    float4 z = make_float4(0.f, 0.f, 0.f, 0.f);
    float4* ai = (float4*)s->Ai;
    float4* at = (float4*)s->At;
    float4* ar = (float4*)s->Ar;
    for (size_t i = idx; i < nf4; i += stride) {
        ai[i] = z; at[i] = z; ar[i] = z;
    }
    if (idx < (size_t)NG * HID / 4) ((float4*)s->pool)[idx] = z;
    if (idx < 2048) s->hist[idx] = 0;
    if (idx == 0) {
        s->st.prefix = 0;
        s->st.kk = KTOP;
        s->st.tie_count = 0;
    }
}

// ---------------------------------------------------------------------------
// GEMM: C[M x 128] = epilogue( A[M x K] (+2*H) @ W[K x 128] + bias )
// Block tile 64 x 128, BK = 32, 256 threads, thread tile 8 x 4.
// ---------------------------------------------------------------------------
template<int K, bool ADD2H, bool RELU, bool ADDIN>
__global__ __launch_bounds__(256)
void gemm_k(const float* __restrict__ A, const float* __restrict__ Hh,
            const float* __restrict__ W, const float* __restrict__ bias,
            const float* __restrict__ addin, float* __restrict__ Cout, int M)
{
    __shared__ float As[64][33];
    __shared__ float4 Bs[32][32];

    const int m0  = blockIdx.x * 64;
    const int tid = threadIdx.x;
    const int tN  = tid & 31;
    const int tM  = tid >> 5;

    float acc[8][4];
#pragma unroll
    for (int i = 0; i < 8; i++)
#pragma unroll
        for (int j = 0; j < 4; j++) acc[i][j] = 0.f;

    for (int k0 = 0; k0 < K; k0 += 32) {
        // load A tile (64 rows x 32 k) as 512 float4s
#pragma unroll
        for (int l = 0; l < 2; l++) {
            int f = tid + l * 256;
            int r = f >> 3;
            int kc = (f & 7) * 4;
            int m = m0 + r;
            float4 v = make_float4(0.f, 0.f, 0.f, 0.f);
            if (m < M) {
                v = *(const float4*)&A[(size_t)m * K + k0 + kc];
                if (ADD2H) {
                    float4 hv = *(const float4*)&Hh[(size_t)m * K + k0 + kc];
                    v.x += 2.f * hv.x; v.y += 2.f * hv.y;
                    v.z += 2.f * hv.z; v.w += 2.f * hv.w;
                }
            }
            As[r][kc + 0] = v.x; As[r][kc + 1] = v.y;
            As[r][kc + 2] = v.z; As[r][kc + 3] = v.w;
        }
        // load B tile (32 k x 128 n) as 1024 float4s
#pragma unroll
        for (int l = 0; l < 4; l++) {
            int g = tid + l * 256;
            int kr = g >> 5;
            int c4 = g & 31;
            Bs[kr][c4] = *(const float4*)&W[(size_t)(k0 + kr) * 128 + c4 * 4];
        }
        __syncthreads();

#pragma unroll
        for (int kk = 0; kk < 32; kk++) {
            float4 bv = Bs[kk][tN];
#pragma unroll
            for (int i = 0; i < 8; i++) {
                float a = As[tM * 8 + i][kk];
                acc[i][0] += a * bv.x;
                acc[i][1] += a * bv.y;
                acc[i][2] += a * bv.z;
                acc[i][3] += a * bv.w;
            }
        }
        __syncthreads();
    }

    const float4 bvz = *(const float4*)&bias[tN * 4];
#pragma unroll
    for (int i = 0; i < 8; i++) {
        int m = m0 + tM * 8 + i;
        if (m < M) {
            float4 v;
            v.x = acc[i][0] + bvz.x;
            v.y = acc[i][1] + bvz.y;
            v.z = acc[i][2] + bvz.z;
            v.w = acc[i][3] + bvz.w;
            if (RELU) {
                v.x = fmaxf(v.x, 0.f); v.y = fmaxf(v.y, 0.f);
                v.z = fmaxf(v.z, 0.f); v.w = fmaxf(v.w, 0.f);
            }
            if (ADDIN) {
                float4 a4 = *(const float4*)&addin[(size_t)m * 128 + tN * 4];
                v.x += a4.x; v.y += a4.y; v.z += a4.z; v.w += a4.w;
            }
            *(float4*)&Cout[(size_t)m * 128 + tN * 4] = v;
        }
    }
}

// ---------------------------------------------------------------------------
// scatter (weight 1): agg[col] += h[row]
// ---------------------------------------------------------------------------
__global__ void scatter_ones(const int* __restrict__ row, const int* __restrict__ col,
                             const float* __restrict__ h, float* __restrict__ out)
{
    int e = blockIdx.x * 8 + (threadIdx.x >> 5);
    if (e >= EE) return;
    int lane = threadIdx.x & 31;
    int r = __ldg(&row[e]);
    int c = __ldg(&col[e]);
    float4 v = *(const float4*)(h + (size_t)r * HID + lane * 4);
    red4(out + (size_t)c * HID + lane * 4, v);
}

// ---------------------------------------------------------------------------
// per-edge dot: ew[e] = <inv_x[row], inv_x[col]>
// ---------------------------------------------------------------------------
__global__ void ew_kernel(const int* __restrict__ row, const int* __restrict__ col,
                          const float* __restrict__ X, float* __restrict__ ew)
{
    int e = blockIdx.x * 8 + (threadIdx.x >> 5);
    if (e >= EE) return;
    int lane = threadIdx.x & 31;
    int r = __ldg(&row[e]);
    int c = __ldg(&col[e]);
    float4 a = *(const float4*)(X + (size_t)r * HID + lane * 4);
    float4 b = *(const float4*)(X + (size_t)c * HID + lane * 4);
    float s = a.x * b.x + a.y * b.y + a.z * b.z + a.w * b.w;
#pragma unroll
    for (int off = 16; off >= 1; off >>= 1)
        s += __shfl_xor_sync(0xFFFFFFFFu, s, off);
    if (lane == 0) ew[e] = s;
}

// ---------------------------------------------------------------------------
// radix-select histogram pass
// ---------------------------------------------------------------------------
__global__ void hist_kernel(const float* __restrict__ ew, unsigned* __restrict__ hist,
                            const SelState* __restrict__ st, int pass)
{
    __shared__ unsigned sh[2048];
    for (int i = threadIdx.x; i < 2048; i += blockDim.x) sh[i] = 0;
    __syncthreads();
    unsigned pref = st->prefix;
    int stride = gridDim.x * blockDim.x;
    for (int e = blockIdx.x * blockDim.x + threadIdx.x; e < EE; e += stride) {
        unsigned u = fkey(ew[e]);
        if (pass == 0) {
            atomicAdd(&sh[u >> 21], 1u);
        } else if (pass == 1) {
            if ((u >> 21) == pref) atomicAdd(&sh[(u >> 10) & 2047u], 1u);
        } else {
            if ((u >> 10) == pref) atomicAdd(&sh[u & 1023u], 1u);
        }
    }
    __syncthreads();
    for (int i = threadIdx.x; i < 2048; i += blockDim.x)
        if (sh[i]) atomicAdd(&hist[i], sh[i]);
}

// ---------------------------------------------------------------------------
// suffix-scan of histogram; pick bucket, update state; zeroes hist for next use
// ---------------------------------------------------------------------------
__global__ void scan_kernel(unsigned* __restrict__ hist, SelState* __restrict__ st,
                            int nbins, int bits, int last)
{
    __shared__ unsigned a[2048], b[2048];
    __shared__ int bstar;
    int tid = threadIdx.x;
    for (int i = tid; i < 2048; i += blockDim.x) {
        a[i] = (i < nbins) ? hist[i] : 0u;
        hist[i] = 0u;
    }
    __syncthreads();
    unsigned* src = a;
    unsigned* dst = b;
    for (int off = 1; off < nbins; off <<= 1) {
        for (int i = tid; i < nbins; i += blockDim.x)
            dst[i] = src[i] + ((i + off < nbins) ? src[i + off] : 0u);
        __syncthreads();
        unsigned* t = src; src = dst; dst = t;
    }
    int kk = st->kk;
    for (int i = tid; i < nbins; i += blockDim.x) {
        unsigned Si = src[i];
        unsigned Sn = (i + 1 < nbins) ? src[i + 1] : 0u;
        if (Si >= (unsigned)kk && Sn < (unsigned)kk) bstar = i;
    }
    __syncthreads();
    if (tid == 0) {
        int bs = bstar;
        unsigned greater = (bs + 1 < nbins) ? src[bs + 1] : 0u;
        st->kk = kk - (int)greater;
        st->prefix = (st->prefix << bits) | (unsigned)bs;
        if (last) {
            st->threshold = st->prefix;
            st->needed = st->kk;
        }
    }
}

// ---------------------------------------------------------------------------
// flag edges strictly above threshold; collect ties
// ---------------------------------------------------------------------------
__global__ void flag_kernel(const float* __restrict__ ew, unsigned char* __restrict__ flag,
                            int* __restrict__ tie, SelState* __restrict__ st)
{
    unsigned T = st->threshold;
    int stride = gridDim.x * blockDim.x;
    for (int e = blockIdx.x * blockDim.x + threadIdx.x; e < EE; e += stride) {
        unsigned u = fkey(ew[e]);
        flag[e] = (u > T) ? (unsigned char)1 : (unsigned char)0;
        if (u == T) {
            int p = atomicAdd(&st->tie_count, 1);
            if (p < MAX_TIES) tie[p] = e;
        }
    }
}

// ---------------------------------------------------------------------------
// pick `needed` lowest-index ties (matches jax.lax.top_k stability)
// ---------------------------------------------------------------------------
__global__ void tie_resolve(int* __restrict__ tie, unsigned char* __restrict__ flag,
                            const SelState* __restrict__ st)
{
    __shared__ int s[MAX_TIES];
    int C = st->tie_count;
    if (C > MAX_TIES) C = MAX_TIES;
    int nd = st->needed;
    int tid = threadIdx.x;
    if (C <= nd) {
        for (int i = tid; i < C; i += blockDim.x) flag[tie[i]] = 1;
        return;
    }
    for (int i = tid; i < C; i += blockDim.x) s[i] = tie[i];
    __syncthreads();
    for (int ph = 0; ph < C; ph++) {
        for (int i = 2 * tid + (ph & 1); i + 1 < C; i += 2 * blockDim.x) {
            if (s[i] > s[i + 1]) { int t = s[i]; s[i] = s[i + 1]; s[i + 1] = t; }
        }
        __syncthreads();
    }
    for (int i = tid; i < nd; i += blockDim.x) flag[s[i]] = 1;
}

// ---------------------------------------------------------------------------
// weighted scatter into top / remaining aggregates
// ---------------------------------------------------------------------------
__global__ void scatter_sel(const int* __restrict__ row, const int* __restrict__ col,
                            const float* __restrict__ h, const float* __restrict__ ew,
                            const unsigned char* __restrict__ flag,
                            float* __restrict__ At, float* __restrict__ Ar)
{
    int e = blockIdx.x * 8 + (threadIdx.x >> 5);
    if (e >= EE) return;
    int lane = threadIdx.x & 31;
    int r = __ldg(&row[e]);
    int c = __ldg(&col[e]);
    float w = __ldg(&ew[e]);
    float4 v = *(const float4*)(h + (size_t)r * HID + lane * 4);
    v.x *= w; v.y *= w; v.z *= w; v.w *= w;
    float* dst = flag[e] ? At : Ar;
    red4(dst + (size_t)c * HID + lane * 4, v);
}

// ---------------------------------------------------------------------------
// pooling: pooled[batch[n]] += xs[n]   (batch sorted -> run-length flush)
// ---------------------------------------------------------------------------
#define NPB 512
__global__ void pool_kernel(const float* __restrict__ xs, const int* __restrict__ batch,
                            float* __restrict__ pooled)
{
    int f = threadIdx.x;
    int n0 = blockIdx.x * NPB;
    if (n0 >= NN) return;
    int n1 = n0 + NPB;
    if (n1 > NN) n1 = NN;
    int cur = batch[n0];
    float acc = 0.f;
    for (int n = n0; n < n1; n++) {
        int b = batch[n];
        if (b != cur) {
            atomicAdd(&pooled[cur * HID + f], acc);
            acc = 0.f;
            cur = b;
        }
        acc += xs[(size_t)n * HID + f];
    }
    atomicAdd(&pooled[cur * HID + f], acc);
}

// ---------------------------------------------------------------------------
// head: p = relu(pooled@post_W+post_b); logits = p@ro_W+ro_b; log_softmax
// ---------------------------------------------------------------------------
__global__ void head_kernel(const float* __restrict__ pool,
                            const float* __restrict__ pW, const float* __restrict__ pb,
                            const float* __restrict__ rW, const float* __restrict__ rb,
                            float* __restrict__ out)
{
    __shared__ float rowv[HID], p[HID], lg[NCLS];
    int g = blockIdx.x, t = threadIdx.x;
    rowv[t] = pool[g * HID + t];
    __syncthreads();
    float s = pb[t];
#pragma unroll 8
    for (int k = 0; k < HID; k++) s += rowv[k] * pW[k * HID + t];
    p[t] = fmaxf(s, 0.f);
    __syncthreads();
    if (t < NCLS) {
        float s2 = rb[t];
#pragma unroll 8
        for (int k = 0; k < HID; k++) s2 += p[k] * rW[k * NCLS + t];
        lg[t] = s2;
    }
    __syncthreads();
    if (t == 0) {
        float mx = lg[0];
        for (int j = 1; j < NCLS; j++) mx = fmaxf(mx, lg[j]);
        float se = 0.f;
        for (int j = 0; j < NCLS; j++) se += expf(lg[j] - mx);
        float l = logf(se) + mx;
        for (int j = 0; j < NCLS; j++) out[g * NCLS + j] = lg[j] - l;
    }
}

// ---------------------------------------------------------------------------
// launch
// ---------------------------------------------------------------------------
extern "C" void kernel_launch(void* const* d_in, const int* in_sizes, int n_in,
                              void* d_out, int out_size)
{
    (void)in_sizes; (void)n_in; (void)out_size;
    const float* x     = (const float*)d_in[0];
    const int*   ei    = (const int*)d_in[1];
    const int*   row   = ei;
    const int*   col   = ei + EE;
    const int*   batch = (const int*)d_in[2];
    const float* preW  = (const float*)d_in[3];
    const float* preB  = (const float*)d_in[4];
    const int LW = 2 * HID * HID, LB = 2 * HID;   // last layer (index 2)
    const float* c1W1 = (const float*)d_in[5]  + LW;
    const float* c1b1 = (const float*)d_in[6]  + LB;
    const float* c1W2 = (const float*)d_in[7]  + LW;
    const float* c1b2 = (const float*)d_in[8]  + LB;
    const float* c3W1 = (const float*)d_in[9]  + LW;
    const float* c3b1 = (const float*)d_in[10] + LB;
    const float* c3W2 = (const float*)d_in[11] + LW;
    const float* c3b2 = (const float*)d_in[12] + LB;
    const float* c4W1 = (const float*)d_in[13] + LW;
    const float* c4b1 = (const float*)d_in[14] + LB;
    const float* c4W2 = (const float*)d_in[15] + LW;
    const float* c4b2 = (const float*)d_in[16] + LB;
    const float* postW = (const float*)d_in[17];
    const float* postB = (const float*)d_in[18];
    const float* roW   = (const float*)d_in[19];
    const float* roB   = (const float*)d_in[20];
    float* out = (float*)d_out;

    Scratch* s = nullptr;
    cudaGetSymbolAddress((void**)&s, g_s);

    const int GB = (NN + 63) / 64;           // gemm blocks
    const int EB = (EE + 7) / 8;             // edge-warp blocks

    zero_init<<<4096, 256>>>(s);

    // h = x @ pre_W + pre_b
    gemm_k<FIN, false, false, false><<<GB, 256>>>(x, nullptr, preW, preB, nullptr, s->h, NN);

    // invariance branch (only layer 2 matters)
    scatter_ones<<<EB, 256>>>(row, col, s->h, s->Ai);
    gemm_k<HID, true,  true,  false><<<GB, 256>>>(s->Ai, s->h, c3W1, c3b1, nullptr, s->T, NN);
    gemm_k<HID, false, true,  false><<<GB, 256>>>(s->T, nullptr, c3W2, c3b2, nullptr, s->X, NN);

    // per-edge weights
    ew_kernel<<<EB, 256>>>(row, col, s->X, s->ew);

    // exact top-k (k = 400000) radix select
    hist_kernel<<<1024, 256>>>(s->ew, s->hist, &s->st, 0);
    scan_kernel<<<1, 1024>>>(s->hist, &s->st, 2048, 11, 0);
    hist_kernel<<<1024, 256>>>(s->ew, s->hist, &s->st, 1);
    scan_kernel<<<1, 1024>>>(s->hist, &s->st, 2048, 11, 0);
    hist_kernel<<<1024, 256>>>(s->ew, s->hist, &s->st, 2);
    scan_kernel<<<1, 1024>>>(s->hist, &s->st, 1024, 10, 1);
    flag_kernel<<<2048, 256>>>(s->ew, s->flag, s->tie, &s->st);
    tie_resolve<<<1, 1024>>>(s->tie, s->flag, &s->st);

    // weighted scatters for both branches
    scatter_sel<<<EB, 256>>>(row, col, s->h, s->ew, s->flag, s->At, s->Ar);

    // branch 1 (top edges, c1):  x1 -> X
    gemm_k<HID, true,  true,  false><<<GB, 256>>>(s->At, s->h, c1W1, c1b1, nullptr, s->T, NN);
    gemm_k<HID, false, true,  false><<<GB, 256>>>(s->T, nullptr, c1W2, c1b2, nullptr, s->X, NN);

    // branch 2 (remaining edges, c4): X = relu(x2) + x1
    gemm_k<HID, true,  true,  false><<<GB, 256>>>(s->Ar, s->h, c4W1, c4b1, nullptr, s->T, NN);
    gemm_k<HID, false, true,  true ><<<GB, 256>>>(s->T, nullptr, c4W2, c4b2, s->X, s->X, NN);

    // pool + head
    pool_kernel<<<(NN + NPB - 1) / NPB, HID>>>(s->X, batch, s->pool);
    head_kernel<<<NG, HID>>>(s->pool, postW, postB, roW, roB, out);
}